// round 1
// baseline (speedup 1.0000x reference)
#include <cuda_runtime.h>

// Closed-form reduction of the circuit:
//   out[b][w] = prod_{j=0..w} cos(inputs[b][j])
// (RZ is diagonal -> no effect on <Z>; CNOT chain maps Z_w -> Z_0...Z_w;
//  product state factorizes the expectation.)
//
// B = 8192 rows, n = 10 wires. One thread per row: load 10 floats,
// running prefix product of cosines, store 10 floats. Fully unrolled.

#ifndef NWIRES
#define NWIRES 10
#endif

__global__ void __launch_bounds__(256)
quantum_prefix_cos_kernel(const float* __restrict__ inputs,
                          float* __restrict__ out,
                          int B)
{
    int b = blockIdx.x * blockDim.x + threadIdx.x;
    if (b >= B) return;

    const float* row = inputs + (long long)b * NWIRES;
    float*       o   = out    + (long long)b * NWIRES;

    float acc = 1.0f;
#pragma unroll
    for (int j = 0; j < NWIRES; j++) {
        acc *= cosf(row[j]);
        o[j] = acc;
    }
}

extern "C" void kernel_launch(void* const* d_in, const int* in_sizes, int n_in,
                              void* d_out, int out_size)
{
    const float* inputs = (const float*)d_in[0];   // (B, 10) float32
    // d_in[1] = rz_params (10,) -- provably unused in the closed form.
    float* out = (float*)d_out;                    // (B, 10) float32

    int B = in_sizes[0] / NWIRES;                  // 8192
    int threads = 256;
    int blocks = (B + threads - 1) / threads;      // 32
    quantum_prefix_cos_kernel<<<blocks, threads>>>(inputs, out, B);
}